// round 16
// baseline (speedup 1.0000x reference)
#include <cuda_runtime.h>
#include <cuda_bf16.h>
#include <cstdint>

#define M_DIM 16384
#define N_DIM 4096
#define K_DIM 4096
#define NCHUNK 4

#if defined(__CUDA_ARCH__) && (defined(__CUDA_ARCH_FEAT_SM103_ALL) || defined(__CUDA_ARCH_FEAT_SM100_ALL) || defined(__CUDA_ARCH_FEAT_SM101_ALL))
#define HAS_TC 1
#else
#define HAS_TC 0
#endif

// Scratch (zero-initialized at module load; absmax atomicMax is idempotent
// across graph replays with identical inputs)
__device__ __nv_bfloat16 g_qx[(size_t)M_DIM * K_DIM];
__device__ __nv_bfloat16 g_qw[(size_t)N_DIM * K_DIM];
__device__ unsigned g_absmax_bits[8];

#define NX (M_DIM * K_DIM)
#define NW (N_DIM * K_DIM)
#define ABS_X_BLOCKS 1024
#define ABS_W_BLOCKS 512
#define QNT_X_BLOCKS 8192
#define QNT_W_BLOCKS 2048

// ---------------------------------------------------------------------------
__global__ void absmax_kernel(const float* __restrict__ x, const float* __restrict__ w) {
    __shared__ unsigned smax[5];
    if (threadIdx.x < 5) smax[threadIdx.x] = 0u;
    __syncthreads();

    const int is_w = blockIdx.x >= ABS_X_BLOCKS;
    const float* src = is_w ? w : x;
    const int n = is_w ? NW : NX;
    const int nblk = is_w ? ABS_W_BLOCKS : ABS_X_BLOCKS;
    const int bid = is_w ? (blockIdx.x - ABS_X_BLOCKS) : blockIdx.x;

    size_t stride = (size_t)nblk * blockDim.x * 4;
    size_t base = ((size_t)bid * blockDim.x + threadIdx.x) * 4;
    int c = is_w ? 4 : (int)((base & 4095) >> 10);
    float m = 0.f;
#pragma unroll 4
    for (size_t e = base; e < (size_t)n; e += stride) {
        float4 v = *(const float4*)(src + e);
        m = fmaxf(m, fmaxf(fmaxf(fabsf(v.x), fabsf(v.y)),
                           fmaxf(fabsf(v.z), fabsf(v.w))));
    }
    atomicMax(&smax[c], __float_as_uint(m));
    __syncthreads();
    if (threadIdx.x < 5) atomicMax(&g_absmax_bits[threadIdx.x], smax[threadIdx.x]);
}

__device__ __forceinline__ float quant_scale(int slot) {
    return fmaxf(__uint_as_float(g_absmax_bits[slot]) * (1.0f / 127.0f), 1e-8f);
}

__global__ void quant_kernel(const float* __restrict__ x, const float* __restrict__ w) {
    const int is_w = blockIdx.x >= QNT_X_BLOCKS;
    float inv[NCHUNK];
    if (is_w) {
        float iw = 1.0f / quant_scale(4);
#pragma unroll
        for (int c = 0; c < NCHUNK; c++) inv[c] = iw;
    } else {
#pragma unroll
        for (int c = 0; c < NCHUNK; c++) inv[c] = 1.0f / quant_scale(c);
    }
    const float* src = is_w ? w : x;
    __nv_bfloat16* dst = is_w ? g_qw : g_qx;
    const int n = is_w ? NW : NX;
    const int nblk = is_w ? QNT_W_BLOCKS : QNT_X_BLOCKS;
    const int bid = is_w ? (blockIdx.x - QNT_X_BLOCKS) : blockIdx.x;

    size_t stride = (size_t)nblk * blockDim.x * 4;
    size_t base = ((size_t)bid * blockDim.x + threadIdx.x) * 4;
#pragma unroll 4
    for (size_t e = base; e < (size_t)n; e += stride) {
        int c = (int)((e & 4095) >> 10);
        float4 v = *(const float4*)(src + e);
        float q0 = fminf(fmaxf(rintf(v.x * inv[c]), -127.f), 127.f);
        float q1 = fminf(fmaxf(rintf(v.y * inv[c]), -127.f), 127.f);
        float q2 = fminf(fmaxf(rintf(v.z * inv[c]), -127.f), 127.f);
        float q3 = fminf(fmaxf(rintf(v.w * inv[c]), -127.f), 127.f);
        __nv_bfloat162 p0, p1;
        p0.x = __float2bfloat16_rn(q0); p0.y = __float2bfloat16_rn(q1);
        p1.x = __float2bfloat16_rn(q2); p1.y = __float2bfloat16_rn(q3);
        *(__nv_bfloat162*)(&dst[e])     = p0;
        *(__nv_bfloat162*)(&dst[e + 2]) = p1;
    }
}

// ===========================================================================
// Warp-specialized cg1 tcgen05 GEMM (round-11 structure — best measured; at
// the LTS delivery ceiling). 256x256 tile, 3 stages x 64KB, grid (16,64).
// 384 threads: tid<256 producers (cp.async + noinc arrive); tid 256-383
// consumer WG (warp 8 = elect-one MMA issuer; 4 warps rescale + epilogue).
// ===========================================================================
#define BT 256
#define SK 64
#define STAGES 3
#define NITER (K_DIM / SK)            // 64
#define A_STAGE_BYTES (256 * 128)
#define B_STAGE_BYTES (256 * 128)
#define STAGE_BYTES (A_STAGE_BYTES + B_STAGE_BYTES)
#define SMEM_STAGE0 1024
#define SMEM_TOTAL (SMEM_STAGE0 + STAGES * STAGE_BYTES)  // 197632

#define MMA_IDESC ((8u << 24) | (32u << 17) | (1u << 10) | (1u << 7) | (1u << 4))

static constexpr uint64_t DESC_BASE_SW128 =
    (uint64_t(2) << 61) | (uint64_t(1) << 46) | (uint64_t(64) << 32) | (uint64_t(1) << 16);

__device__ __forceinline__ uint32_t smem_u32(const void* p) {
    return (uint32_t)__cvta_generic_to_shared(p);
}
__device__ __forceinline__ uint32_t swz(uint32_t o) { return o ^ ((o >> 3) & 0x70); }

__device__ __forceinline__ void cp16(uint32_t sdst, const void* gsrc) {
    asm volatile("cp.async.cg.shared.global [%0], [%1], 16;\n" :: "r"(sdst), "l"(gsrc));
}
// .noinc is load-bearing (R9 post-mortem: default variant self-cancels)
#define CPA_ARRIVE(mb) asm volatile("cp.async.mbarrier.arrive.noinc.shared::cta.b64 [%0];" :: "r"(mb) : "memory")

#define MBAR_INIT(a, n) asm volatile("mbarrier.init.shared.b64 [%0], %1;" :: "r"(a), "r"(n) : "memory")
#define MBAR_INVAL(a)   asm volatile("mbarrier.inval.shared.b64 [%0];" :: "r"(a) : "memory")

__device__ __forceinline__ void mbar_wait(uint32_t addr, uint32_t parity) {
    asm volatile(
        "{\n\t.reg .pred P;\n\t"
        "WAIT_%=:\n\t"
        "mbarrier.try_wait.parity.acquire.cta.shared::cta.b64 P, [%0], %1, 0x989680;\n\t"
        "@P bra.uni DONE_%=;\n\t"
        "bra.uni WAIT_%=;\n\t"
        "DONE_%=:\n\t}"
        :: "r"(addr), "r"(parity) : "memory");
}

__device__ __forceinline__ bool elect1() {
    uint32_t r;
    asm volatile(
        "{\n\t.reg .pred p;\n\t"
        "elect.sync _|p, 0xFFFFFFFF;\n\t"
        "selp.b32 %0, 1, 0, p;\n\t}"
        : "=r"(r));
    return r != 0;
}

#if HAS_TC
#define TC_ALLOC(sp, n)   asm volatile("tcgen05.alloc.cta_group::1.sync.aligned.shared::cta.b32 [%0], %1;" :: "r"(sp), "r"(n) : "memory")
#define TC_DEALLOC(t, n)  asm volatile("tcgen05.dealloc.cta_group::1.sync.aligned.b32 %0, %1;" :: "r"(t), "r"(n))
#define TC_RELINQ()       asm volatile("tcgen05.relinquish_alloc_permit.cta_group::1.sync.aligned;")
#define TC_COMMIT(mb)     asm volatile("tcgen05.commit.cta_group::1.mbarrier::arrive::one.shared::cluster.b64 [%0];" :: "r"(mb) : "memory")
#define TC_WAIT_LD()      asm volatile("tcgen05.wait::ld.sync.aligned;" ::: "memory")
#define TC_WAIT_ST()      asm volatile("tcgen05.wait::st.sync.aligned;" ::: "memory")
#define TC_FENCE_BEFORE() asm volatile("tcgen05.fence::before_thread_sync;" ::: "memory")
#define TC_FENCE_AFTER()  asm volatile("tcgen05.fence::after_thread_sync;" ::: "memory")
#define FENCE_ASYNC()     asm volatile("fence.proxy.async.shared::cta;" ::: "memory")
#define NAMED_BAR(id, n)  asm volatile("bar.sync %0, %1;" :: "r"(id), "r"(n) : "memory")

__device__ __forceinline__ void mma_f16_ss(uint32_t d, uint64_t ad, uint64_t bd,
                                           uint32_t idesc, uint32_t en) {
    asm volatile(
        "{\n\t.reg .pred p;\n\t"
        "setp.ne.u32 p, %4, 0;\n\t"
        "tcgen05.mma.cta_group::1.kind::f16 [%0], %1, %2, %3, {%5,%5,%5,%5}, p;\n\t}"
        :: "r"(d), "l"(ad), "l"(bd), "r"(idesc), "r"(en), "r"(0u) : "memory");
}

#define TC_LD32(r, addr) \
    asm volatile( \
        "tcgen05.ld.sync.aligned.32x32b.x32.b32 " \
        "{%0,%1,%2,%3,%4,%5,%6,%7,%8,%9,%10,%11,%12,%13,%14,%15," \
        "%16,%17,%18,%19,%20,%21,%22,%23,%24,%25,%26,%27,%28,%29,%30,%31}, [%32];" \
        : "=r"((r)[0]),"=r"((r)[1]),"=r"((r)[2]),"=r"((r)[3]),"=r"((r)[4]),"=r"((r)[5]),"=r"((r)[6]),"=r"((r)[7]), \
          "=r"((r)[8]),"=r"((r)[9]),"=r"((r)[10]),"=r"((r)[11]),"=r"((r)[12]),"=r"((r)[13]),"=r"((r)[14]),"=r"((r)[15]), \
          "=r"((r)[16]),"=r"((r)[17]),"=r"((r)[18]),"=r"((r)[19]),"=r"((r)[20]),"=r"((r)[21]),"=r"((r)[22]),"=r"((r)[23]), \
          "=r"((r)[24]),"=r"((r)[25]),"=r"((r)[26]),"=r"((r)[27]),"=r"((r)[28]),"=r"((r)[29]),"=r"((r)[30]),"=r"((r)[31]) \
        : "r"(addr))

#define TC_ST32(addr, r) \
    asm volatile( \
        "tcgen05.st.sync.aligned.32x32b.x32.b32 [%0], " \
        "{%1,%2,%3,%4,%5,%6,%7,%8,%9,%10,%11,%12,%13,%14,%15,%16," \
        "%17,%18,%19,%20,%21,%22,%23,%24,%25,%26,%27,%28,%29,%30,%31,%32};" \
        :: "r"(addr), \
           "r"((r)[0]),"r"((r)[1]),"r"((r)[2]),"r"((r)[3]),"r"((r)[4]),"r"((r)[5]),"r"((r)[6]),"r"((r)[7]), \
           "r"((r)[8]),"r"((r)[9]),"r"((r)[10]),"r"((r)[11]),"r"((r)[12]),"r"((r)[13]),"r"((r)[14]),"r"((r)[15]), \
           "r"((r)[16]),"r"((r)[17]),"r"((r)[18]),"r"((r)[19]),"r"((r)[20]),"r"((r)[21]),"r"((r)[22]),"r"((r)[23]), \
           "r"((r)[24]),"r"((r)[25]),"r"((r)[26]),"r"((r)[27]),"r"((r)[28]),"r"((r)[29]),"r"((r)[30]),"r"((r)[31]) \
        : "memory")
#endif  // HAS_TC

__global__ void __launch_bounds__(384, 1) gemm_tc_kernel(const float* __restrict__ bias,
                                                         float* __restrict__ out) {
#if HAS_TC
    extern __shared__ char smem[];
    const uint32_t sbase = smem_u32(smem);
    const int tid = threadIdx.x;
    const int bn = blockIdx.x, bm = blockIdx.y;

    const uint32_t mb_full  = sbase + 16;   // [0..2], count 256
    const uint32_t mb_empty = sbase + 40;   // [0..2], count 1
    const uint32_t mb_chunk = sbase + 64;
    const uint32_t mb_final = sbase + 72;

    if (tid == 0) {
#pragma unroll
        for (int s = 0; s < STAGES; s++) {
            MBAR_INIT(mb_full + s * 8, 256);
            MBAR_INIT(mb_empty + s * 8, 1);
        }
        MBAR_INIT(mb_chunk, 1);
        MBAR_INIT(mb_final, 1);
    }
    if (tid >= 256 && tid < 288) { TC_ALLOC(sbase, 512); TC_RELINQ(); }
    __syncthreads();

    uint32_t tmem_base;
    asm volatile("ld.shared.b32 %0, [%1];" : "=r"(tmem_base) : "r"(sbase));

    float cs[NCHUNK];
    {
        float sw = quant_scale(4);
#pragma unroll
        for (int c = 0; c < NCHUNK; c++) cs[c] = quant_scale(c) * sw;
    }

    if (tid < 256) {
        // ================= PRODUCERS =================
        const __nv_bfloat16* gA = g_qx + (size_t)(bm * BT) * K_DIM;
        const __nv_bfloat16* gB = g_qw + (size_t)(bn * BT) * K_DIM;
        for (int t = 0; t < NITER; ++t) {
            const int slot = t % STAGES;
            if (t >= STAGES)
                mbar_wait(mb_empty + slot * 8, (uint32_t)(((t / STAGES) - 1) & 1));
            const uint32_t abase = sbase + SMEM_STAGE0 + slot * STAGE_BYTES;
            const uint32_t bbase = abase + A_STAGE_BYTES;
            const int kt = t * SK;
#pragma unroll
            for (int j = 0; j < 8; j++) {
                int ch = tid + j * 256;
                int row = ch >> 3, c16 = ch & 7;
                cp16(abase + swz(row * 128 + c16 * 16),
                     gA + (size_t)row * K_DIM + kt + c16 * 8);
            }
#pragma unroll
            for (int j = 0; j < 8; j++) {
                int ch = tid + j * 256;
                int row = ch >> 3, c16 = ch & 7;
                cp16(bbase + swz(row * 128 + c16 * 16),
                     gB + (size_t)row * K_DIM + kt + c16 * 8);
            }
            CPA_ARRIVE(mb_full + slot * 8);
        }
    } else {
        // ================= CONSUMER WARPGROUP (128 threads) =================
        const int ctid = tid - 256;
        const int cwarp = ctid >> 5;
        const uint32_t cwoff = (uint32_t)cwarp << 21;

        for (int seg = 0; seg < 4; ++seg) {
            if (cwarp == 0) {
                const int i0 = seg * 16;
#pragma unroll 1
                for (int i = i0; i < i0 + 16; ++i) {
                    const int slot = i % STAGES;
                    mbar_wait(mb_full + slot * 8, (uint32_t)((i / STAGES) & 1));
                    if (elect1()) {
                        FENCE_ASYNC();
                        const uint32_t abase = sbase + SMEM_STAGE0 + slot * STAGE_BYTES;
                        const uint64_t ad = DESC_BASE_SW128 | ((uint64_t)(abase >> 4) & 0x3FFF);
                        const uint64_t bd = DESC_BASE_SW128 | ((uint64_t)((abase + A_STAGE_BYTES) >> 4) & 0x3FFF);
#pragma unroll
                        for (int h = 0; h < 2; h++) {
                            const uint32_t d = tmem_base + h * 256u;
                            const uint64_t adh = ad + h * 1024;
#pragma unroll
                            for (int k = 0; k < 4; k++) {
                                const uint32_t en = (i == 0 && k == 0) ? 0u : 1u;
                                mma_f16_ss(d, adh + k * 2, bd + k * 2, MMA_IDESC, en);
                            }
                        }
                        TC_COMMIT(mb_empty + slot * 8);
                    }
                    __syncwarp();
                }
                if (elect1()) {
                    if (seg < 3) TC_COMMIT(mb_chunk);
                    else         TC_COMMIT(mb_final);
                }
                __syncwarp();
            }

            if (seg < 3) {
                // rescale: all 4 consumer warps, 4 col-blocks per wait
                mbar_wait(mb_chunk, (uint32_t)(seg & 1));
                TC_FENCE_AFTER();
                const float ratio = cs[seg] / cs[seg + 1];
#pragma unroll
                for (int g4 = 0; g4 < 4; g4++) {
                    uint32_t r[4][32];
#pragma unroll
                    for (int b = 0; b < 4; b++)
                        TC_LD32(r[b], tmem_base + (g4 * 4 + b) * 32);
                    TC_WAIT_LD();
#pragma unroll
                    for (int b = 0; b < 4; b++)
#pragma unroll
                        for (int j = 0; j < 32; j++)
                            r[b][j] = __float_as_uint(__uint_as_float(r[b][j]) * ratio);
#pragma unroll
                    for (int b = 0; b < 4; b++)
                        TC_ST32(tmem_base + (g4 * 4 + b) * 32 + cwoff, r[b]);
                    TC_WAIT_ST();
                }
                TC_FENCE_BEFORE();
                NAMED_BAR(1, 128);
                TC_FENCE_AFTER();
            }
        }

        // epilogue: 4 col-blocks per wait
        mbar_wait(mb_final, 0u);
        TC_FENCE_AFTER();
        {
            const float fs = cs[3];
            const float* brow = bias + bn * BT;
#pragma unroll
            for (int h = 0; h < 2; h++) {
                const int row = bm * BT + h * 128 + ctid;
                float* orow = out + (size_t)row * N_DIM + bn * BT;
#pragma unroll
                for (int nb = 0; nb < 8; nb += 4) {
                    uint32_t a[4][32];
#pragma unroll
                    for (int b = 0; b < 4; b++)
                        TC_LD32(a[b], tmem_base + h * 256 + (nb + b) * 32);
                    TC_WAIT_LD();
#pragma unroll
                    for (int b = 0; b < 4; b++) {
#pragma unroll
                        for (int j = 0; j < 32; j += 4) {
                            float4 bb = *(const float4*)(brow + (nb + b) * 32 + j);
                            float4 v;
                            v.x = __uint_as_float(a[b][j + 0]) * fs + bb.x;
                            v.y = __uint_as_float(a[b][j + 1]) * fs + bb.y;
                            v.z = __uint_as_float(a[b][j + 2]) * fs + bb.z;
                            v.w = __uint_as_float(a[b][j + 3]) * fs + bb.w;
                            *(float4*)(orow + (nb + b) * 32 + j) = v;
                        }
                    }
                }
            }
            TC_FENCE_BEFORE();
        }
        NAMED_BAR(1, 128);
        if (cwarp == 0) {
            TC_DEALLOC(tmem_base, 512);
            if (elect1()) { MBAR_INVAL(mb_chunk); MBAR_INVAL(mb_final); }
        }
    }
#endif  // HAS_TC
}

// ---------------------------------------------------------------------------
extern "C" void kernel_launch(void* const* d_in, const int* in_sizes, int n_in,
                              void* d_out, int out_size) {
    const float* x = (const float*)d_in[0];
    const float* w = (const float*)d_in[1];
    const float* bias = (const float*)d_in[2];
    float* out = (float*)d_out;

    absmax_kernel<<<ABS_X_BLOCKS + ABS_W_BLOCKS, 256>>>(x, w);
    quant_kernel<<<QNT_X_BLOCKS + QNT_W_BLOCKS, 256>>>(x, w);

    cudaFuncSetAttribute(gemm_tc_kernel,
                         cudaFuncAttributeMaxDynamicSharedMemorySize, SMEM_TOTAL);
    dim3 gtc(N_DIM / BT, M_DIM / BT);   // (16, 64)
    gemm_tc_kernel<<<gtc, 384, SMEM_TOTAL>>>(bias, out);
}

// round 17
// speedup vs baseline: 1.0823x; 1.0823x over previous
#include <cuda_runtime.h>
#include <cuda_bf16.h>
#include <cstdint>

#define M_DIM 16384
#define N_DIM 4096
#define K_DIM 4096
#define NCHUNK 4

#if defined(__CUDA_ARCH__) && (defined(__CUDA_ARCH_FEAT_SM103_ALL) || defined(__CUDA_ARCH_FEAT_SM100_ALL) || defined(__CUDA_ARCH_FEAT_SM101_ALL))
#define HAS_TC 1
#else
#define HAS_TC 0
#endif

// Scratch
__device__ __nv_bfloat16 g_qx[(size_t)M_DIM * K_DIM];
__device__ __nv_bfloat16 g_qw[(size_t)N_DIM * K_DIM];
__device__ unsigned g_absmax_bits[8];

#define NX (M_DIM * K_DIM)
#define NW (N_DIM * K_DIM)
#define ABS_X_BLOCKS 1024
#define ABS_W_BLOCKS 512
#define QNT_X_BLOCKS 8192
#define QNT_W_BLOCKS 2048

// ---------------------------------------------------------------------------
__global__ void zero_kernel() {
    if (threadIdx.x < 8) g_absmax_bits[threadIdx.x] = 0u;
}

__global__ void absmax_kernel(const float* __restrict__ x, const float* __restrict__ w) {
    __shared__ unsigned smax[5];
    if (threadIdx.x < 5) smax[threadIdx.x] = 0u;
    __syncthreads();

    const int is_w = blockIdx.x >= ABS_X_BLOCKS;
    const float* src = is_w ? w : x;
    const int n = is_w ? NW : NX;
    const int nblk = is_w ? ABS_W_BLOCKS : ABS_X_BLOCKS;
    const int bid = is_w ? (blockIdx.x - ABS_X_BLOCKS) : blockIdx.x;

    size_t stride = (size_t)nblk * blockDim.x * 4;
    size_t base = ((size_t)bid * blockDim.x + threadIdx.x) * 4;
    int c = is_w ? 4 : (int)((base & 4095) >> 10);
    float m = 0.f;
    for (size_t e = base; e < (size_t)n; e += stride) {
        float4 v = *(const float4*)(src + e);
        m = fmaxf(m, fmaxf(fmaxf(fabsf(v.x), fabsf(v.y)),
                           fmaxf(fabsf(v.z), fabsf(v.w))));
    }
    atomicMax(&smax[c], __float_as_uint(m));
    __syncthreads();
    if (threadIdx.x < 5) atomicMax(&g_absmax_bits[threadIdx.x], smax[threadIdx.x]);
}

__device__ __forceinline__ float quant_scale(int slot) {
    return fmaxf(__uint_as_float(g_absmax_bits[slot]) * (1.0f / 127.0f), 1e-8f);
}

__global__ void quant_kernel(const float* __restrict__ x, const float* __restrict__ w) {
    const int is_w = blockIdx.x >= QNT_X_BLOCKS;
    float inv[NCHUNK];
    if (is_w) {
        float iw = 1.0f / quant_scale(4);
#pragma unroll
        for (int c = 0; c < NCHUNK; c++) inv[c] = iw;
    } else {
#pragma unroll
        for (int c = 0; c < NCHUNK; c++) inv[c] = 1.0f / quant_scale(c);
    }
    const float* src = is_w ? w : x;
    __nv_bfloat16* dst = is_w ? g_qw : g_qx;
    const int n = is_w ? NW : NX;
    const int nblk = is_w ? QNT_W_BLOCKS : QNT_X_BLOCKS;
    const int bid = is_w ? (blockIdx.x - QNT_X_BLOCKS) : blockIdx.x;

    size_t stride = (size_t)nblk * blockDim.x * 4;
    size_t base = ((size_t)bid * blockDim.x + threadIdx.x) * 4;
    for (size_t e = base; e < (size_t)n; e += stride) {
        int c = (int)((e & 4095) >> 10);
        float4 v = *(const float4*)(src + e);
        float q0 = fminf(fmaxf(rintf(v.x * inv[c]), -127.f), 127.f);
        float q1 = fminf(fmaxf(rintf(v.y * inv[c]), -127.f), 127.f);
        float q2 = fminf(fmaxf(rintf(v.z * inv[c]), -127.f), 127.f);
        float q3 = fminf(fmaxf(rintf(v.w * inv[c]), -127.f), 127.f);
        __nv_bfloat162 p0, p1;
        p0.x = __float2bfloat16_rn(q0); p0.y = __float2bfloat16_rn(q1);
        p1.x = __float2bfloat16_rn(q2); p1.y = __float2bfloat16_rn(q3);
        *(__nv_bfloat162*)(&dst[e])     = p0;
        *(__nv_bfloat162*)(&dst[e + 2]) = p1;
    }
}

// ===========================================================================
// Warp-specialized cg1 tcgen05 GEMM, 256x256 tile, 3 stages x 64KB.
// 384 threads: tid<256 producers (cp.async + noinc mbarrier arrive).
// tid 256-383 consumer warpgroup: warp 8 (all lanes, elect-one issue) drives
// MMAs; all 4 consumer warps do TMEM rescale + epilogue.
// ===========================================================================
#define BT 256
#define SK 64
#define STAGES 3
#define NITER (K_DIM / SK)            // 64
#define A_STAGE_BYTES (256 * 128)     // 32KB
#define B_STAGE_BYTES (256 * 128)     // 32KB
#define STAGE_BYTES (A_STAGE_BYTES + B_STAGE_BYTES)
#define SMEM_STAGE0 1024
#define SMEM_TOTAL (SMEM_STAGE0 + STAGES * STAGE_BYTES)  // 197632

#define MMA_IDESC ((8u << 24) | (32u << 17) | (1u << 10) | (1u << 7) | (1u << 4))

static constexpr uint64_t DESC_BASE_SW128 =
    (uint64_t(2) << 61) | (uint64_t(1) << 46) | (uint64_t(64) << 32) | (uint64_t(1) << 16);

__device__ __forceinline__ uint32_t smem_u32(const void* p) {
    return (uint32_t)__cvta_generic_to_shared(p);
}
__device__ __forceinline__ uint32_t swz(uint32_t o) { return o ^ ((o >> 3) & 0x70); }

__device__ __forceinline__ void cp16(uint32_t sdst, const void* gsrc) {
    asm volatile("cp.async.cg.shared.global [%0], [%1], 16;\n" :: "r"(sdst), "l"(gsrc));
}
// CRITICAL: .noinc — default variant pre-increments pending count and the
// deferred arrive nets to zero, so the barrier would never flip (R8/R9 hang).
#define CPA_ARRIVE(mb) asm volatile("cp.async.mbarrier.arrive.noinc.shared::cta.b64 [%0];" :: "r"(mb) : "memory")

#define MBAR_INIT(a, n) asm volatile("mbarrier.init.shared.b64 [%0], %1;" :: "r"(a), "r"(n) : "memory")
#define MBAR_INVAL(a)   asm volatile("mbarrier.inval.shared.b64 [%0];" :: "r"(a) : "memory")

__device__ __forceinline__ void mbar_wait(uint32_t addr, uint32_t parity) {
    asm volatile(
        "{\n\t.reg .pred P;\n\t"
        "WAIT_%=:\n\t"
        "mbarrier.try_wait.parity.acquire.cta.shared::cta.b64 P, [%0], %1, 0x989680;\n\t"
        "@P bra.uni DONE_%=;\n\t"
        "bra.uni WAIT_%=;\n\t"
        "DONE_%=:\n\t}"
        :: "r"(addr), "r"(parity) : "memory");
}

__device__ __forceinline__ bool elect1() {
    uint32_t r;
    asm volatile(
        "{\n\t.reg .pred p;\n\t"
        "elect.sync _|p, 0xFFFFFFFF;\n\t"
        "selp.b32 %0, 1, 0, p;\n\t}"
        : "=r"(r));
    return r != 0;
}

#if HAS_TC
#define TC_ALLOC(sp, n)   asm volatile("tcgen05.alloc.cta_group::1.sync.aligned.shared::cta.b32 [%0], %1;" :: "r"(sp), "r"(n) : "memory")
#define TC_DEALLOC(t, n)  asm volatile("tcgen05.dealloc.cta_group::1.sync.aligned.b32 %0, %1;" :: "r"(t), "r"(n))
#define TC_RELINQ()       asm volatile("tcgen05.relinquish_alloc_permit.cta_group::1.sync.aligned;")
#define TC_COMMIT(mb)     asm volatile("tcgen05.commit.cta_group::1.mbarrier::arrive::one.shared::cluster.b64 [%0];" :: "r"(mb) : "memory")
#define TC_WAIT_LD()      asm volatile("tcgen05.wait::ld.sync.aligned;" ::: "memory")
#define TC_WAIT_ST()      asm volatile("tcgen05.wait::st.sync.aligned;" ::: "memory")
#define TC_FENCE_BEFORE() asm volatile("tcgen05.fence::before_thread_sync;" ::: "memory")
#define TC_FENCE_AFTER()  asm volatile("tcgen05.fence::after_thread_sync;" ::: "memory")
#define FENCE_ASYNC()     asm volatile("fence.proxy.async.shared::cta;" ::: "memory")
#define NAMED_BAR(id, n)  asm volatile("bar.sync %0, %1;" :: "r"(id), "r"(n) : "memory")

__device__ __forceinline__ void mma_f16_ss(uint32_t d, uint64_t ad, uint64_t bd,
                                           uint32_t idesc, uint32_t en) {
    asm volatile(
        "{\n\t.reg .pred p;\n\t"
        "setp.ne.u32 p, %4, 0;\n\t"
        "tcgen05.mma.cta_group::1.kind::f16 [%0], %1, %2, %3, {%5,%5,%5,%5}, p;\n\t}"
        :: "r"(d), "l"(ad), "l"(bd), "r"(idesc), "r"(en), "r"(0u) : "memory");
}

#define TC_LD32(r, addr) \
    asm volatile( \
        "tcgen05.ld.sync.aligned.32x32b.x32.b32 " \
        "{%0,%1,%2,%3,%4,%5,%6,%7,%8,%9,%10,%11,%12,%13,%14,%15," \
        "%16,%17,%18,%19,%20,%21,%22,%23,%24,%25,%26,%27,%28,%29,%30,%31}, [%32];" \
        : "=r"((r)[0]),"=r"((r)[1]),"=r"((r)[2]),"=r"((r)[3]),"=r"((r)[4]),"=r"((r)[5]),"=r"((r)[6]),"=r"((r)[7]), \
          "=r"((r)[8]),"=r"((r)[9]),"=r"((r)[10]),"=r"((r)[11]),"=r"((r)[12]),"=r"((r)[13]),"=r"((r)[14]),"=r"((r)[15]), \
          "=r"((r)[16]),"=r"((r)[17]),"=r"((r)[18]),"=r"((r)[19]),"=r"((r)[20]),"=r"((r)[21]),"=r"((r)[22]),"=r"((r)[23]), \
          "=r"((r)[24]),"=r"((r)[25]),"=r"((r)[26]),"=r"((r)[27]),"=r"((r)[28]),"=r"((r)[29]),"=r"((r)[30]),"=r"((r)[31]) \
        : "r"(addr))

#define TC_ST32(addr, r) \
    asm volatile( \
        "tcgen05.st.sync.aligned.32x32b.x32.b32 [%0], " \
        "{%1,%2,%3,%4,%5,%6,%7,%8,%9,%10,%11,%12,%13,%14,%15,%16," \
        "%17,%18,%19,%20,%21,%22,%23,%24,%25,%26,%27,%28,%29,%30,%31,%32};" \
        :: "r"(addr), \
           "r"((r)[0]),"r"((r)[1]),"r"((r)[2]),"r"((r)[3]),"r"((r)[4]),"r"((r)[5]),"r"((r)[6]),"r"((r)[7]), \
           "r"((r)[8]),"r"((r)[9]),"r"((r)[10]),"r"((r)[11]),"r"((r)[12]),"r"((r)[13]),"r"((r)[14]),"r"((r)[15]), \
           "r"((r)[16]),"r"((r)[17]),"r"((r)[18]),"r"((r)[19]),"r"((r)[20]),"r"((r)[21]),"r"((r)[22]),"r"((r)[23]), \
           "r"((r)[24]),"r"((r)[25]),"r"((r)[26]),"r"((r)[27]),"r"((r)[28]),"r"((r)[29]),"r"((r)[30]),"r"((r)[31]) \
        : "memory")
#endif  // HAS_TC

__global__ void __launch_bounds__(384, 1) gemm_tc_kernel(const float* __restrict__ bias,
                                                         float* __restrict__ out) {
#if HAS_TC
    extern __shared__ char smem[];
    const uint32_t sbase = smem_u32(smem);
    const int tid = threadIdx.x;
    const int bn = blockIdx.x, bm = blockIdx.y;

    const uint32_t mb_full  = sbase + 16;   // [0..2], count 256
    const uint32_t mb_empty = sbase + 40;   // [0..2], count 1
    const uint32_t mb_chunk = sbase + 64;
    const uint32_t mb_final = sbase + 72;

    if (tid == 0) {
#pragma unroll
        for (int s = 0; s < STAGES; s++) {
            MBAR_INIT(mb_full + s * 8, 256);
            MBAR_INIT(mb_empty + s * 8, 1);
        }
        MBAR_INIT(mb_chunk, 1);
        MBAR_INIT(mb_final, 1);
    }
    if (tid >= 256 && tid < 288) { TC_ALLOC(sbase, 512); TC_RELINQ(); }
    __syncthreads();

    uint32_t tmem_base;
    asm volatile("ld.shared.b32 %0, [%1];" : "=r"(tmem_base) : "r"(sbase));

    float cs[NCHUNK];
    {
        float sw = quant_scale(4);
#pragma unroll
        for (int c = 0; c < NCHUNK; c++) cs[c] = quant_scale(c) * sw;
    }

    if (tid < 256) {
        // ================= PRODUCERS =================
        const __nv_bfloat16* gA = g_qx + (size_t)(bm * BT) * K_DIM;
        const __nv_bfloat16* gB = g_qw + (size_t)(bn * BT) * K_DIM;
        for (int t = 0; t < NITER; ++t) {
            const int slot = t % STAGES;
            if (t >= STAGES)
                mbar_wait(mb_empty + slot * 8, (uint32_t)(((t / STAGES) - 1) & 1));
            const uint32_t abase = sbase + SMEM_STAGE0 + slot * STAGE_BYTES;
            const uint32_t bbase = abase + A_STAGE_BYTES;
            const int kt = t * SK;
#pragma unroll
            for (int j = 0; j < 8; j++) {
                int ch = tid + j * 256;
                int row = ch >> 3, c16 = ch & 7;
                cp16(abase + swz(row * 128 + c16 * 16),
                     gA + (size_t)row * K_DIM + kt + c16 * 8);
            }
#pragma unroll
            for (int j = 0; j < 8; j++) {
                int ch = tid + j * 256;
                int row = ch >> 3, c16 = ch & 7;
                cp16(bbase + swz(row * 128 + c16 * 16),
                     gB + (size_t)row * K_DIM + kt + c16 * 8);
            }
            CPA_ARRIVE(mb_full + slot * 8);
        }
    } else {
        // ================= CONSUMER WARPGROUP (128 threads) =================
        const int ctid = tid - 256;
        const int cwarp = ctid >> 5;
        const uint32_t cwoff = (uint32_t)cwarp << 21;

        // 4 chunk segments of 16 stages each; rescale between segments
        for (int seg = 0; seg < 4; ++seg) {
            if (cwarp == 0) {
                // ENTIRE warp 8 runs the issue loop; one elected lane issues.
                const int i0 = seg * 16;
#pragma unroll 1
                for (int i = i0; i < i0 + 16; ++i) {
                    const int slot = i % STAGES;
                    mbar_wait(mb_full + slot * 8, (uint32_t)((i / STAGES) & 1));
                    if (elect1()) {
                        FENCE_ASYNC();
                        const uint32_t abase = sbase + SMEM_STAGE0 + slot * STAGE_BYTES;
                        const uint64_t ad = DESC_BASE_SW128 | ((uint64_t)(abase >> 4) & 0x3FFF);
                        const uint64_t bd = DESC_BASE_SW128 | ((uint64_t)((abase + A_STAGE_BYTES) >> 4) & 0x3FFF);
#pragma unroll
                        for (int h = 0; h < 2; h++) {
                            const uint32_t d = tmem_base + h * 256u;
                            const uint64_t adh = ad + h * 1024;
#pragma unroll
                            for (int k = 0; k < 4; k++) {
                                const uint32_t en = (i == 0 && k == 0) ? 0u : 1u;
                                mma_f16_ss(d, adh + k * 2, bd + k * 2, MMA_IDESC, en);
                            }
                        }
                        TC_COMMIT(mb_empty + slot * 8);
                    }
                    __syncwarp();
                }
                if (elect1()) {
                    if (seg < 3) TC_COMMIT(mb_chunk);
                    else         TC_COMMIT(mb_final);
                }
                __syncwarp();
            }

            if (seg < 3) {
                // rescale: all 4 consumer warps, converged per warp
                mbar_wait(mb_chunk, (uint32_t)(seg & 1));
                TC_FENCE_AFTER();
                const float ratio = cs[seg] / cs[seg + 1];
#pragma unroll
                for (int g = 0; g < 8; g++) {
                    uint32_t r[2][32];
                    TC_LD32(r[0], tmem_base + (g * 2) * 32);
                    TC_LD32(r[1], tmem_base + (g * 2 + 1) * 32);
                    TC_WAIT_LD();
#pragma unroll
                    for (int b = 0; b < 2; b++)
#pragma unroll
                        for (int j = 0; j < 32; j++)
                            r[b][j] = __float_as_uint(__uint_as_float(r[b][j]) * ratio);
                    TC_ST32(tmem_base + (g * 2) * 32 + cwoff, r[0]);
                    TC_ST32(tmem_base + (g * 2 + 1) * 32 + cwoff, r[1]);
                    TC_WAIT_ST();
                }
                TC_FENCE_BEFORE();
                NAMED_BAR(1, 128);
                TC_FENCE_AFTER();
            }
        }

        // epilogue
        mbar_wait(mb_final, 0u);
        TC_FENCE_AFTER();
        {
            const float fs = cs[3];
            const float* brow = bias + bn * BT;
#pragma unroll
            for (int h = 0; h < 2; h++) {
                const int row = bm * BT + h * 128 + ctid;
                float* orow = out + (size_t)row * N_DIM + bn * BT;
#pragma unroll
                for (int nb = 0; nb < 8; nb += 2) {
                    uint32_t a0[32], a1[32];
                    TC_LD32(a0, tmem_base + h * 256 + nb * 32);
                    TC_LD32(a1, tmem_base + h * 256 + (nb + 1) * 32);
                    TC_WAIT_LD();
#pragma unroll
                    for (int j = 0; j < 32; j += 4) {
                        float4 bb = *(const float4*)(brow + nb * 32 + j);
                        float4 v;
                        v.x = __uint_as_float(a0[j + 0]) * fs + bb.x;
                        v.y = __uint_as_float(a0[j + 1]) * fs + bb.y;
                        v.z = __uint_as_float(a0[j + 2]) * fs + bb.z;
                        v.w = __uint_as_float(a0[j + 3]) * fs + bb.w;
                        *(float4*)(orow + nb * 32 + j) = v;
                    }
#pragma unroll
                    for (int j = 0; j < 32; j += 4) {
                        float4 bb = *(const float4*)(brow + (nb + 1) * 32 + j);
                        float4 v;
                        v.x = __uint_as_float(a1[j + 0]) * fs + bb.x;
                        v.y = __uint_as_float(a1[j + 1]) * fs + bb.y;
                        v.z = __uint_as_float(a1[j + 2]) * fs + bb.z;
                        v.w = __uint_as_float(a1[j + 3]) * fs + bb.w;
                        *(float4*)(orow + (nb + 1) * 32 + j) = v;
                    }
                }
            }
            TC_FENCE_BEFORE();
        }
        NAMED_BAR(1, 128);
        if (cwarp == 0) {
            TC_DEALLOC(tmem_base, 512);
            if (elect1()) { MBAR_INVAL(mb_chunk); MBAR_INVAL(mb_final); }
        }
    }
#endif  // HAS_TC
}

// ---------------------------------------------------------------------------
extern "C" void kernel_launch(void* const* d_in, const int* in_sizes, int n_in,
                              void* d_out, int out_size) {
    const float* x = (const float*)d_in[0];
    const float* w = (const float*)d_in[1];
    const float* bias = (const float*)d_in[2];
    float* out = (float*)d_out;

    zero_kernel<<<1, 32>>>();
    absmax_kernel<<<ABS_X_BLOCKS + ABS_W_BLOCKS, 256>>>(x, w);
    quant_kernel<<<QNT_X_BLOCKS + QNT_W_BLOCKS, 256>>>(x, w);

    cudaFuncSetAttribute(gemm_tc_kernel,
                         cudaFuncAttributeMaxDynamicSharedMemorySize, SMEM_TOTAL);
    dim3 gtc(N_DIM / BT, M_DIM / BT);   // (16, 64)
    gemm_tc_kernel<<<gtc, 384, SMEM_TOTAL>>>(bias, out);
}